// round 13
// baseline (speedup 1.0000x reference)
#include <cuda_runtime.h>
#include <cuda_bf16.h>
#include <cstdint>

// ─── Problem constants ────────────────────────────────────────────────
#define NROWS 8192       // 1024 clusters * 8
#define DIM   128
#define TM    128
#define TN    128
#define NMT   64                  // 64*65/2 = 2080 triangle tiles
#define NCTAS 128                 // 32 row-pairs x 4 CTAs (17+16+16+16 = 65)

#define A_BYTES (TM * 256)
#define B_BYTES (TN * 256)
#define NBUF    5                 // B ring depth (drift-safe minimum)
#define SMEM_REQ (A_BYTES + NBUF * B_BYTES)   // 192 KB dynamic

__device__ __align__(16) __nv_bfloat16 g_ebf[NROWS * DIM];
__device__ float g_sqnorm[NROWS];
__device__ unsigned g_posu[NROWS];   // bits of squared hardest-positive (atomicMax)
__device__ unsigned g_negu[NROWS];   // bits of squared hardest-negative (atomicMin)

// ─── PTX helpers (generic-target-safe) ────────────────────────────────
__device__ __forceinline__ uint32_t smem_u32(const void* p) {
    uint32_t a;
    asm("{ .reg .u64 t; cvta.to.shared.u64 t, %1; cvt.u32.u64 %0, t; }" : "=r"(a) : "l"(p));
    return a;
}
__device__ __forceinline__ void cp16(uint32_t dst, const void* src) {
    asm volatile("cp.async.cg.shared.global [%0], [%1], 16;" :: "r"(dst), "l"(src));
}
__device__ __forceinline__ void cp_commit() {
    asm volatile("cp.async.commit_group;" ::: "memory");
}
template <int N> __device__ __forceinline__ void cp_wait() {
    asm volatile("cp.async.wait_group %0;" :: "n"(N) : "memory");
}
#define LDSM_X4(r0, r1, r2, r3, addr) \
    asm volatile("ldmatrix.sync.aligned.m8n8.x4.shared.b16 {%0,%1,%2,%3}, [%4];" \
                 : "=r"(r0), "=r"(r1), "=r"(r2), "=r"(r3) : "r"(addr))
#define MMA16816(c, a, b0, b1) \
    asm volatile("mma.sync.aligned.m16n8k16.row.col.f32.bf16.bf16.f32 " \
                 "{%0,%1,%2,%3},{%4,%5,%6,%7},{%8,%9},{%0,%1,%2,%3};" \
                 : "+f"((c)[0]), "+f"((c)[1]), "+f"((c)[2]), "+f"((c)[3]) \
                 : "r"((a)[0]), "r"((a)[1]), "r"((a)[2]), "r"((a)[3]), "r"(b0), "r"(b1))

// ─── Kernel 1: fp32 -> bf16 convert + norms + init atomic targets ────
__global__ void convert_kernel(const float* __restrict__ E) {
    int gid = blockIdx.x * 256 + threadIdx.x;   // 131072 threads: 16 per row
    if (gid < NROWS) { g_posu[gid] = 0u; g_negu[gid] = 0x7F800000u; }
    int row = gid >> 4, hseg = gid & 15;        // 8 elems per thread (2 x float4)
    float s = 0.f;
    uint2 pk[2];
#pragma unroll
    for (int q = 0; q < 2; q++) {
        float4 v = *reinterpret_cast<const float4*>(E + (size_t)row * DIM + hseg * 8 + q * 4);
        __nv_bfloat16 bx = __float2bfloat16_rn(v.x), by = __float2bfloat16_rn(v.y);
        __nv_bfloat16 bz = __float2bfloat16_rn(v.z), bw = __float2bfloat16_rn(v.w);
        float fx = __bfloat162float(bx), fy = __bfloat162float(by);
        float fz = __bfloat162float(bz), fw = __bfloat162float(bw);
        s += fx * fx + fy * fy + fz * fz + fw * fw;
        pk[q].x = ((uint32_t)__bfloat16_as_ushort(by) << 16) | __bfloat16_as_ushort(bx);
        pk[q].y = ((uint32_t)__bfloat16_as_ushort(bw) << 16) | __bfloat16_as_ushort(bz);
    }
    *reinterpret_cast<uint4*>(g_ebf + (size_t)row * DIM + hseg * 8) =
        make_uint4(pk[0].x, pk[0].y, pk[1].x, pk[1].y);
#pragma unroll
    for (int d = 8; d > 0; d >>= 1) s += __shfl_xor_sync(0xFFFFFFFFu, s, d);
    if (hseg == 0) g_sqnorm[row] = s;
}

// ─── Kernel 2: pipelined triangle HMMA GEMM + dual mining ────────────
extern __shared__ char dsm[];

__global__ __launch_bounds__(256, 1) void hmma_kernel() {
    __shared__ float s_norm[NBUF][TN];
    __shared__ float s_p[4][TM];
    __shared__ float s_n[4][TM];

    const uint32_t as_u32 = smem_u32(dsm);
    uint32_t bs_u32[NBUF], nrm_u32[NBUF];
#pragma unroll
    for (int i = 0; i < NBUF; i++) {
        bs_u32[i]  = smem_u32(dsm + A_BYTES + i * B_BYTES);
        nrm_u32[i] = smem_u32(s_norm[i]);
    }

    const int tid  = threadIdx.x;
    const int wid  = tid >> 5;
    const int lane = tid & 31;
    const int warp_m = wid >> 2;      // 0..1
    const int warp_n = wid & 3;       // 0..3

    // ── Row-pair schedule: pair p = {row p, row 63-p}, 65 tiles, 4 CTAs ──
    const int p  = blockIdx.x >> 2;
    const int q  = blockIdx.x & 3;
    const int r1 = 64 - p;                       // tiles in first row
    const int Lstart = (q == 0) ? 0 : 17 + 16 * (q - 1);
    const int NT = (q == 0) ? 17 : 16;
    auto tile_coords = [&](int L, int& m, int& n) {
        if (L < r1) { m = p; n = p + L; }
        else        { m = 63 - p; n = (63 - p) + (L - r1); }
    };

    // ── Loaders ──
    auto issue_a = [&](int m) {
        const char* src = (const char*)g_ebf + (size_t)m * TM * 256;
#pragma unroll
        for (int qq = 0; qq < 8; qq++) {
            int idx = tid + qq * 256;
            int r = idx >> 4, c = idx & 15;
            cp16(as_u32 + r * 256 + ((c ^ (r & 7)) << 4), src + (size_t)r * 256 + c * 16);
        }
    };
    auto issue_b = [&](int n, int slot) {
        int jb = n * TN;
        const char* src = (const char*)g_ebf + (size_t)jb * 256;
        uint32_t dst = bs_u32[slot];
#pragma unroll
        for (int qq = 0; qq < 8; qq++) {
            int idx = tid + qq * 256;
            int r = idx >> 4, c = idx & 15;
            cp16(dst + r * 256 + ((c ^ (r & 7)) << 4), src + (size_t)r * 256 + c * 16);
        }
        if (tid < 32)
            cp16(nrm_u32[slot] + tid * 16, (const char*)(g_sqnorm + jb) + tid * 16);
    };

    // ── Per-thread row metadata ──
    float ni[4][2];
    int   ci[4][2];
    auto load_rowmeta = [&](int m) {
#pragma unroll
        for (int mi = 0; mi < 4; mi++)
#pragma unroll
            for (int h = 0; h < 2; h++) {
                int gi = m * TM + warp_m * 64 + mi * 16 + (lane >> 2) + h * 8;
                ni[mi][h] = g_sqnorm[gi];
                ci[mi][h] = gi >> 3;
            }
    };

    float pm[4][2], nm[4][2];
#pragma unroll
    for (int mi = 0; mi < 4; mi++)
#pragma unroll
        for (int h = 0; h < 2; h++) { pm[mi][h] = 0.f; nm[mi][h] = 3.0e38f; }

    auto flush_rows = [&](int m) {
        __syncthreads();
#pragma unroll
        for (int mi = 0; mi < 4; mi++)
#pragma unroll
            for (int h = 0; h < 2; h++) {
                float pp = pm[mi][h], nn = nm[mi][h];
                pp = fmaxf(pp, __shfl_xor_sync(0xFFFFFFFFu, pp, 1));
                pp = fmaxf(pp, __shfl_xor_sync(0xFFFFFFFFu, pp, 2));
                nn = fminf(nn, __shfl_xor_sync(0xFFFFFFFFu, nn, 1));
                nn = fminf(nn, __shfl_xor_sync(0xFFFFFFFFu, nn, 2));
                if ((lane & 3) == 0) {
                    int r = warp_m * 64 + mi * 16 + (lane >> 2) + h * 8;
                    s_p[warp_n][r] = pp;
                    s_n[warp_n][r] = nn;
                }
            }
        __syncthreads();
        if (tid < TM) {
            float pp = fmaxf(fmaxf(s_p[0][tid], s_p[1][tid]), fmaxf(s_p[2][tid], s_p[3][tid]));
            float nn = fminf(fminf(s_n[0][tid], s_n[1][tid]), fminf(s_n[2][tid], s_n[3][tid]));
            atomicMax(&g_posu[m * TM + tid], __float_as_uint(pp));
            atomicMin(&g_negu[m * TM + tid], __float_as_uint(nn));
        }
#pragma unroll
        for (int mi = 0; mi < 4; mi++)
#pragma unroll
            for (int h = 0; h < 2; h++) { pm[mi][h] = 0.f; nm[mi][h] = 3.0e38f; }
        __syncthreads();
    };

    // ── ldmatrix address offsets ──
    uint32_t aRow[4], aSwz[4];
#pragma unroll
    for (int mi = 0; mi < 4; mi++) {
        int r = warp_m * 64 + mi * 16 + (lane & 15);
        aRow[mi] = r * 256;
        aSwz[mi] = r & 7;
    }
    uint32_t bRow[2], bSwz[2];
#pragma unroll
    for (int nb2 = 0; nb2 < 2; nb2++) {
        int r = warp_n * 32 + nb2 * 16 + ((lane >> 4) << 3) + (lane & 7);
        bRow[nb2] = r * 256;
        bSwz[nb2] = r & 7;
    }
    const uint32_t aChunkHi = lane >> 4;
    const uint32_t bChunkHi = (lane >> 3) & 1;

    // acc lives ACROSS iterations: written by MMA(t), consumed by epilogue at t+1.
    float acc[4][4][4];

    auto do_mma = [&](int slot) {
#pragma unroll
        for (int mi = 0; mi < 4; mi++)
#pragma unroll
            for (int nb = 0; nb < 4; nb++)
#pragma unroll
                for (int e = 0; e < 4; e++) acc[mi][nb][e] = 0.f;
        const uint32_t ab = as_u32;
        const uint32_t bb = bs_u32[slot];
#pragma unroll
        for (int k = 0; k < 8; k++) {
            uint32_t a[4][4];
#pragma unroll
            for (int mi = 0; mi < 4; mi++) {
                uint32_t ad = ab + aRow[mi] + (((2 * k + aChunkHi) ^ aSwz[mi]) << 4);
                LDSM_X4(a[mi][0], a[mi][1], a[mi][2], a[mi][3], ad);
            }
            uint32_t b[2][4];
#pragma unroll
            for (int nb2 = 0; nb2 < 2; nb2++) {
                uint32_t bd = bb + bRow[nb2] + (((2 * k + bChunkHi) ^ bSwz[nb2]) << 4);
                LDSM_X4(b[nb2][0], b[nb2][1], b[nb2][2], b[nb2][3], bd);
            }
#pragma unroll
            for (int mi = 0; mi < 4; mi++) {
                MMA16816(acc[mi][0], a[mi], b[0][0], b[0][1]);
                MMA16816(acc[mi][1], a[mi], b[0][2], b[0][3]);
                MMA16816(acc[mi][2], a[mi], b[1][0], b[1][1]);
                MMA16816(acc[mi][3], a[mi], b[1][2], b[1][3]);
            }
        }
    };

    auto do_epilogue = [&](int emt, int ent, int slot) {
        const int jt = ent * TN;
        const bool do_cols = (ent != emt);
        float cpx[4][2], cnx[4][2];
#pragma unroll
        for (int nb = 0; nb < 4; nb++) {
            cpx[nb][0] = cpx[nb][1] = 0.f;
            cnx[nb][0] = cnx[nb][1] = 3.0e38f;
        }
#pragma unroll
        for (int nb = 0; nb < 4; nb++) {
            int cl = warp_n * 32 + nb * 8 + ((lane & 3) << 1);
            float nj0 = s_norm[slot][cl], nj1 = s_norm[slot][cl + 1];
            int cj = (jt + cl) >> 3;
#pragma unroll
            for (int mi = 0; mi < 4; mi++)
#pragma unroll
                for (int h = 0; h < 2; h++) {
                    float bs = ni[mi][h];
                    float s0v = fmaxf(fmaf(-2.0f, acc[mi][nb][h * 2 + 0], bs + nj0), 0.0f);
                    float s1v = fmaxf(fmaf(-2.0f, acc[mi][nb][h * 2 + 1], bs + nj1), 0.0f);
                    if (cj == ci[mi][h]) {
                        pm[mi][h] = fmaxf(pm[mi][h], fmaxf(s0v, s1v));
                        cpx[nb][0] = fmaxf(cpx[nb][0], s0v);
                        cpx[nb][1] = fmaxf(cpx[nb][1], s1v);
                    } else {
                        nm[mi][h] = fminf(nm[mi][h], fminf(s0v, s1v));
                        cnx[nb][0] = fminf(cnx[nb][0], s0v);
                        cnx[nb][1] = fminf(cnx[nb][1], s1v);
                    }
                }
        }
        if (do_cols) {
#pragma unroll
            for (int nb = 0; nb < 4; nb++)
#pragma unroll
                for (int c2 = 0; c2 < 2; c2++) {
                    float pp = cpx[nb][c2], nn = cnx[nb][c2];
#pragma unroll
                    for (int d = 4; d <= 16; d <<= 1) {
                        pp = fmaxf(pp, __shfl_xor_sync(0xFFFFFFFFu, pp, d));
                        nn = fminf(nn, __shfl_xor_sync(0xFFFFFFFFu, nn, d));
                    }
                    if (lane < 4) {
                        int j = jt + warp_n * 32 + nb * 8 + lane * 2 + c2;
                        atomicMax(&g_posu[j], __float_as_uint(pp));
                        atomicMin(&g_negu[j], __float_as_uint(nn));
                    }
                }
        }
    };

    // ── Prologue: prime A + 2 B stages ──
    int tm, tn;
    tile_coords(Lstart, tm, tn);
    issue_a(tm);
    issue_b(tn, 0);
    cp_commit();                       // group 0 = A + B0
    {
        int m1, n1;
        tile_coords(Lstart + 1, m1, n1);
        issue_b(n1, 1);
        cp_commit();                   // group 1 = B1
    }
    load_rowmeta(tm);

    int ptm = tm, ptn = tn;
    // ── Main pipelined loop ──
    for (int t = 0; t < NT; t++) {
        if (t + 2 < NT) {
            int im, in_;
            tile_coords(Lstart + t + 2, im, in_);
            issue_b(in_, (t + 2) % NBUF);
            cp_commit();
        }
        if (t + 2 < NT)      cp_wait<2>();
        else if (t + 1 < NT) cp_wait<1>();
        else                 cp_wait<0>();
        __syncthreads();               // all warps past their wait -> tile t visible
        if (t > 0) do_epilogue(ptm, ptn, (t - 1) % NBUF);   // overlaps others' MMA(t)
        if (t > 0 && tm != ptm) {      // row junction (<=1 per CTA)
            flush_rows(ptm);
            issue_a(tm);
            cp_commit();
            cp_wait<0>();
            __syncthreads();
            load_rowmeta(tm);
        }
        do_mma(t % NBUF);
        ptm = tm; ptn = tn;
        if (t + 1 < NT) tile_coords(Lstart + t + 1, tm, tn);
    }
    do_epilogue(ptm, ptn, (NT - 1) % NBUF);
    flush_rows(ptm);
}

// ─── Kernel 3: final reduction ───────────────────────────────────────
__global__ void final_kernel(float* __restrict__ out) {
    __shared__ float red[1024];
    int tid = threadIdx.x;
    float s = 0.f;
    for (int i = tid; i < NROWS; i += 1024) {
        float ap = sqrtf(__uint_as_float(g_posu[i]));
        float an = sqrtf(__uint_as_float(g_negu[i]));
        s += fmaxf(ap - an + 1.0f, 0.0f);
    }
    red[tid] = s;
    __syncthreads();
    for (int st = 512; st > 0; st >>= 1) {
        if (tid < st) red[tid] += red[tid + st];
        __syncthreads();
    }
    if (tid == 0) out[0] = red[0] / (float)NROWS;
}

extern "C" void kernel_launch(void* const* d_in, const int* in_sizes, int n_in,
                              void* d_out, int out_size) {
    const float* E = (const float*)d_in[0];
    float* out = (float*)d_out;

    cudaFuncSetAttribute(hmma_kernel, cudaFuncAttributeMaxDynamicSharedMemorySize, SMEM_REQ);

    convert_kernel<<<512, 256>>>(E);
    hmma_kernel<<<NCTAS, 256, SMEM_REQ>>>();
    final_kernel<<<1, 1024>>>(out);
}